// round 13
// baseline (speedup 1.0000x reference)
#include <cuda_runtime.h>
#include <cuda_fp16.h>
#include <cstdint>

// ============================================================================
// out[65536,256] = (x[65536,512] @ W[256,512]^T) * 0.125 + 0.1*bias
// R12: single-term fp16 mma.sync, warp-specialized. Producer rewritten as a
// flat 16-slot (4 stages x 4 batches) pipeline with lookahead-2 LDG register
// buffering -> DRAM latency off the critical path. Consumer/barriers = R11.
// ============================================================================

#define KD 512
#define ND 256
#define MROWS 65536
#define BM 128
#define BN 128
#define KB 128                // k-cols per stage (4 subchunks of 32)
#define NS 4                  // KD / KB
#define NPIPE 2
#define THREADS 384

// stage (64KB): A subchunks 4x8K | B subchunks 4x8K
#define STAGE_BYTES 65536
#define BUF0 1024
#define SMEM_TOTAL (BUF0 + NPIPE * STAGE_BYTES)   // 132096
// mbarriers: full[j] at sb + j*8 ; empty[j] at sb + 24 + j*8

// ---- pre-split W fp16: [half 2][kchunk 16] tiles of 8KB, SW64 swizzled ----
__device__ __align__(1024) unsigned char g_w[2 * 16 * 8192];   // 256KB

__device__ __forceinline__ uint32_t swz64(uint32_t o) {
    return o ^ ((o >> 3) & 0x30);
}
__device__ __forceinline__ uint32_t smem_u32(const void* p) {
    uint32_t a;
    asm("{ .reg .u64 t; cvta.to.shared.u64 t, %1; cvt.u32.u64 %0, t; }"
        : "=r"(a) : "l"(p));
    return a;
}
__device__ __forceinline__ void sts64(uint32_t a, uint32_t r0, uint32_t r1) {
    asm volatile("st.shared.v2.b32 [%0], {%1,%2};" :: "r"(a), "r"(r0), "r"(r1)
                 : "memory");
}
// pack (lo arg -> low half, hi arg -> high half) as f16x2
__device__ __forceinline__ uint32_t packf16(float lo, float hi) {
    uint32_t r;
    asm("cvt.rn.f16x2.f32 %0, %1, %2;" : "=r"(r) : "f"(hi), "f"(lo));
    return r;
}

#define MBAR_INIT(a, c) \
    asm volatile("mbarrier.init.shared.b64 [%0], %1;" :: "r"(a), "r"(c) : "memory")
#define MBAR_EXPECT_TX(a, tx) \
    asm volatile("mbarrier.arrive.expect_tx.shared.b64 _, [%0], %1;" \
                 :: "r"(a), "r"(tx) : "memory")
#define MBAR_ARRIVE(a) \
    asm volatile("mbarrier.arrive.shared.b64 _, [%0];" :: "r"(a) : "memory")
#define MBAR_WAIT(a, par) do {                                              \
    asm volatile(                                                           \
        "{\n\t.reg .pred P1;\n\t"                                           \
        "WL_%=:\n\t"                                                        \
        "mbarrier.try_wait.parity.acquire.cta.shared::cta.b64 P1, [%0], %1, 0x989680;\n\t" \
        "@P1 bra.uni WD_%=;\n\t"                                            \
        "bra.uni WL_%=;\n\t"                                                \
        "WD_%=:\n\t}"                                                       \
        :: "r"(a), "r"(par) : "memory");                                    \
} while (0)

#define BULK_G2S(dst, src, sz, mbar) \
    asm volatile("cp.async.bulk.shared::cta.global.mbarrier::complete_tx::bytes " \
                 "[%0], [%1], %2, [%3];" \
                 :: "r"(dst), "l"(src), "r"(sz), "r"(mbar) : "memory")

#define LDSM4(r, addr) \
    asm volatile("ldmatrix.sync.aligned.m8n8.x4.shared.b16 {%0,%1,%2,%3}, [%4];" \
                 : "=r"((r)[0]), "=r"((r)[1]), "=r"((r)[2]), "=r"((r)[3])  \
                 : "r"(addr))

#define MMA(d, a, b0, b1) \
    asm volatile("mma.sync.aligned.m16n8k16.row.col.f32.f16.f16.f32 " \
                 "{%0,%1,%2,%3}, {%4,%5,%6,%7}, {%8,%9}, {%0,%1,%2,%3};" \
                 : "+f"((d)[0]), "+f"((d)[1]), "+f"((d)[2]), "+f"((d)[3]) \
                 : "r"((a)[0]), "r"((a)[1]), "r"((a)[2]), "r"((a)[3]),    \
                   "r"(b0), "r"(b1))

// ============================================================================
// W split: fp32 -> fp16, layout g_w[half][kchunk] 8KB tiles (SW64 inside).
// ============================================================================
__global__ void split_w_kernel(const float* __restrict__ src) {
    const int n4 = ND * KD / 4;                       // 32768
    int i = blockIdx.x * blockDim.x + threadIdx.x;
    if (i >= n4) return;
    float4 v = ((const float4*)src)[i];
    int r = i >> 7;                // W row (n index) 0..255
    int c4 = i & 127;              // float4 within row
    int half = r >> 7;
    int rl = r & 127;
    int kchunk = c4 >> 3;          // 32-col chunk
    int cc = c4 & 7;
    size_t dstoff = (size_t)half * 131072 + (size_t)kchunk * 8192
                  + swz64((uint32_t)(rl * 64 + cc * 8));
    *(uint2*)(g_w + dstoff) = make_uint2(packf16(v.x, v.y), packf16(v.z, v.w));
}

// ============================================================================
// Fused GEMM, warp-specialized, single fp16 term
// ============================================================================
// slot u = stage (u>>2), batch (u&3). batch loads 8 float4/thread.
__device__ __forceinline__ void load_slot(float4 pf[8], const float* x, int u,
                                          int bm, int ptid) {
    const int s = u >> 2;
    const int b = u & 3;
#pragma unroll
    for (int j = 0; j < 8; j++) {
        const int e = ptid + 128 * (8 * b + j);
        const int r = e >> 5;            // row 0..127
        const int c4 = e & 31;           // float4 within 128-col stage
        pf[j] = *(const float4*)(x + (size_t)(bm + r) * KD + s * KB + c4 * 4);
    }
}

__device__ __forceinline__ void cvt_sts_slot(uint32_t bufA, const float4 pf[8],
                                             int u, int ptid) {
    const int b = u & 3;
#pragma unroll
    for (int j = 0; j < 8; j++) {
        const int e = ptid + 128 * (8 * b + j);
        const int r = e >> 5;
        const int c4 = e & 31;
        const uint32_t daddr = (uint32_t)((c4 >> 3) * 8192)
                             + swz64((uint32_t)(r * 64 + (c4 & 7) * 8));
        float4 v = pf[j];
        sts64(bufA + daddr, packf16(v.x, v.y), packf16(v.z, v.w));
    }
}

__global__ void __launch_bounds__(THREADS, 1)
gemm_ws_kernel(const float* __restrict__ x, const float* __restrict__ bias,
               float* __restrict__ out) {
    extern __shared__ __align__(1024) char smem[];
    const uint32_t sb = smem_u32(smem);
    const int tid = threadIdx.x;
    const int wid = tid >> 5;
    const int lane = tid & 31;
    const int bn = blockIdx.x;     // fastest: bn pair adjacent (x L2 reuse)
    const int bm = blockIdx.y * BM;

    if (tid == 0) {
#pragma unroll
        for (int j = 0; j < NPIPE; j++) {
            MBAR_INIT(sb + j * 8, 129);        // full: 128 STS arrivals + expect_tx
            MBAR_INIT(sb + 24 + j * 8, 8);     // empty: 8 consumer warps
        }
        asm volatile("fence.proxy.async.shared::cta;" ::: "memory");
    }
    __syncthreads();

    if (wid >= 8) {
        // ================= PRODUCER (warps 8..11) =================
        // flat 16-slot pipeline, lookahead-2 register buffers (rolling %3)
        const int ptid = tid - 256;
        float4 pf[3][8];
        load_slot(pf[0], x, 0, bm, ptid);
        load_slot(pf[1], x, 1, bm, ptid);

#pragma unroll
        for (int u = 0; u < 4 * NS; u++) {
            const int s = u >> 2;
            const int b = u & 3;
            const int j = s & 1;
            const uint32_t buf = sb + BUF0 + (uint32_t)j * STAGE_BYTES;
            if (b == 0) {
                const int r = s >> 1;
                if (r >= 1) MBAR_WAIT(sb + 24 + j * 8, (uint32_t)((r - 1) & 1));
                if (tid == 256) {
                    MBAR_EXPECT_TX(sb + j * 8, 32768u);
                    BULK_G2S(buf + 32768,
                             g_w + (size_t)bn * 131072 + (size_t)s * 32768,
                             32768u, sb + j * 8);
                }
            }
            if (u + 2 < 4 * NS) load_slot(pf[(u + 2) % 3], x, u + 2, bm, ptid);
            cvt_sts_slot(buf, pf[u % 3], u, ptid);
            if (b == 3) MBAR_ARRIVE(sb + j * 8);
        }
        return;
    }

    // ================= CONSUMER (warps 0..7) =================
    const int wm = wid >> 2;       // 0..1, rows wm*64
    const int wn = wid & 3;        // 0..3, cols wn*32

    const int lrow8 = ((lane >> 3) & 1) * 8 + (lane & 7);
    const int lk16 = (lane >> 4) * 16;
    uint32_t aoff[4], boff[2];
#pragma unroll
    for (int mi = 0; mi < 4; mi++)
        aoff[mi] = (uint32_t)((wm * 64 + mi * 16 + lrow8) * 64 + lk16);
#pragma unroll
    for (int g = 0; g < 2; g++)
        boff[g] = (uint32_t)((wn * 32 + g * 16 + lrow8) * 64 + lk16);

    float acc[4][4][4];
#pragma unroll
    for (int mi = 0; mi < 4; mi++)
#pragma unroll
        for (int ni = 0; ni < 4; ni++)
#pragma unroll
            for (int j = 0; j < 4; j++) acc[mi][ni][j] = 0.0f;

    // double-buffered fragment sets
    uint32_t bht[2][2][4];
    uint32_t ahh[2][4][4];

#pragma unroll 1
    for (int s = 0; s < NS; s++) {
        const int j = s & 1;
        const int r = s >> 1;
        MBAR_WAIT(sb + j * 8, (uint32_t)(r & 1));

        const uint32_t bufA = sb + BUF0 + (uint32_t)j * STAGE_BYTES;
        const uint32_t bufB = bufA + 32768;

        // prefetch group 0 fragments
        {
#pragma unroll
            for (int g = 0; g < 2; g++)
                LDSM4(bht[0][g], bufB + swz64(boff[g]));
#pragma unroll
            for (int mi = 0; mi < 4; mi++)
                LDSM4(ahh[0][mi], bufA + swz64(aoff[mi]));
        }

#pragma unroll
        for (int g4 = 0; g4 < 8; g4++) {           // 8 k16-groups
            const int cb = g4 & 1;
            if (g4 < 7) {
                const int gn = g4 + 1;
                const uint32_t sub = (uint32_t)((gn >> 1) * 8192);
                const uint32_t kadd = (uint32_t)((gn & 1) * 32);
                const int nb = gn & 1;
#pragma unroll
                for (int g = 0; g < 2; g++)
                    LDSM4(bht[nb][g], bufB + sub + swz64(boff[g] + kadd));
#pragma unroll
                for (int mi = 0; mi < 4; mi++)
                    LDSM4(ahh[nb][mi], bufA + sub + swz64(aoff[mi] + kadd));
            }
#pragma unroll
            for (int mi = 0; mi < 4; mi++) {
#pragma unroll
                for (int g = 0; g < 2; g++) {
                    MMA(acc[mi][2 * g],     ahh[cb][mi], bht[cb][g][0], bht[cb][g][2]);
                    MMA(acc[mi][2 * g + 1], ahh[cb][mi], bht[cb][g][1], bht[cb][g][3]);
                }
            }
        }
        if (lane == 0) MBAR_ARRIVE(sb + 24 + j * 8);
    }

    // ---- epilogue ----
    const int quad = lane >> 2;
    const int tq = lane & 3;
    const float scale = 0.125f;
#pragma unroll
    for (int mi = 0; mi < 4; mi++) {
        const int row0 = bm + wm * 64 + mi * 16 + quad;
#pragma unroll
        for (int ni = 0; ni < 4; ni++) {
            const int col = bn * BN + wn * 32 + ni * 8 + tq * 2;
            const float2 bv = *(const float2*)(bias + col);
            float2 o0, o1;
            o0.x = acc[mi][ni][0] * scale + 0.1f * bv.x;
            o0.y = acc[mi][ni][1] * scale + 0.1f * bv.y;
            o1.x = acc[mi][ni][2] * scale + 0.1f * bv.x;
            o1.y = acc[mi][ni][3] * scale + 0.1f * bv.y;
            *(float2*)(out + (size_t)row0 * ND + col) = o0;
            *(float2*)(out + (size_t)(row0 + 8) * ND + col) = o1;
        }
    }
}

// ============================================================================
extern "C" void kernel_launch(void* const* d_in, const int* in_sizes, int n_in,
                              void* d_out, int out_size) {
    const float* x      = (const float*)d_in[0];   // [65536, 512]
    const float* weight = (const float*)d_in[1];   // [256, 512]
    const float* bias   = (const float*)d_in[2];   // [256]
    float* out = (float*)d_out;                    // [65536, 256]

    cudaFuncSetAttribute(gemm_ws_kernel,
                         cudaFuncAttributeMaxDynamicSharedMemorySize, SMEM_TOTAL);

    split_w_kernel<<<128, 256>>>(weight);
    dim3 grid(ND / BN, MROWS / BM);   // (2, 512), bn fastest
    gemm_ws_kernel<<<grid, THREADS, SMEM_TOTAL>>>(x, bias, out);
}